// round 7
// baseline (speedup 1.0000x reference)
#include <cuda_runtime.h>
#include <math.h>
#include <stdint.h>

#define NB    8192      // batch
#define DK    768       // key dim
#define DIM   768       // embedding dim
#define POOL  30
#define PLEN  20
#define TOPK  5
#define HALF  10        // PLEN/2

// ---------------------------------------------------------------------------
// Single fused kernel, one block (256 threads) per batch row.
//  phase 1: 8 warps split the 30 keys; each warp computes dot(q,K_k) AND
//           dot(K_k,K_k) in one pass (K fragment already in regs -> norm
//           kernel eliminated, zero extra loads). sim = dot * rsqrt(kk).
//  phase 2: thread 0 serial top-5 (30-entry scan x5).
//  phase 3: validated gather copy (5 x 60KB, same access pattern as the
//           92.7%-DRAM round-1 gather kernel).
// Grid stays 8192-wide so resident-block store concurrency matches the
// validated gather (round-4 failure was grid=512, not fusion per se).
// ---------------------------------------------------------------------------
__global__ __launch_bounds__(256) void l2p_onepass_kernel(
    const float* __restrict__ xq,
    const float* __restrict__ K,
    const float* __restrict__ p,
    float* __restrict__ out)
{
    const int lane = threadIdx.x & 31;
    const int wInB = threadIdx.x >> 5;           // warp in block (0..7)
    const int b    = blockIdx.x;                 // batch row

    __shared__ float s_sims[32];
    __shared__ int   s_idx[TOPK];

    // ---------------- phase 1: sims (dot + norm fused) ----------------------
    const float4* qrow = reinterpret_cast<const float4*>(xq) + (size_t)b * (DK / 4);
    float4 q[6];
#pragma unroll
    for (int j = 0; j < 6; j++)
        q[j] = __ldg(qrow + j * 32 + lane);

    const float4* K4 = reinterpret_cast<const float4*>(K);
    for (int k = wInB; k < POOL; k += 8) {
        float a = 0.f;   // dot(q, K_k)
        float s = 0.f;   // dot(K_k, K_k)
        const float4* nk = K4 + k * (DK / 4);
#pragma unroll
        for (int j = 0; j < 6; j++) {
            float4 n = __ldg(nk + j * 32 + lane);
            a += q[j].x * n.x + q[j].y * n.y + q[j].z * n.z + q[j].w * n.w;
            s += n.x * n.x + n.y * n.y + n.z * n.z + n.w * n.w;
        }
        // two interleaved butterflies (independent chains -> ILP)
#pragma unroll
        for (int off = 16; off; off >>= 1) {
            a += __shfl_xor_sync(0xFFFFFFFFu, a, off);
            s += __shfl_xor_sync(0xFFFFFFFFu, s, off);
        }
        if (lane == 0)
            s_sims[k] = a * (1.0f / sqrtf(fmaxf(s, 1e-24f)));  // = dot/max(||K||,1e-12)
    }
    __syncthreads();

    // ---------------- phase 2: serial top-5 ---------------------------------
    if (threadIdx.x == 0) {
        unsigned used = 0;
#pragma unroll
        for (int t = 0; t < TOPK; t++) {
            float best = -3.4e38f;
            int   bi   = 0;
#pragma unroll
            for (int k = 0; k < POOL; k++) {
                if ((used >> k) & 1u) continue;
                float v = s_sims[k];
                if (v > best) { best = v; bi = k; }   // strict > => smallest idx on ties
            }
            used |= (1u << bi);
            s_idx[t] = bi;
        }
    }
    __syncthreads();

    // ---------------- phase 3: gather (HBM-write-bound) ---------------------
    const float4* p4   = reinterpret_cast<const float4*>(p);
    float4*       out4 = reinterpret_cast<float4*>(out);
    const int halfN = HALF * DIM / 4;            // 1920 float4 per half

#pragma unroll
    for (int t = 0; t < TOPK; t++) {
        int k = s_idx[t];
        const float4* src = p4 + (size_t)k * (PLEN * DIM / 4);
        size_t base0 = ((size_t)b * (TOPK * HALF) + (size_t)t * HALF) * (DIM / 4);
        size_t base1 = ((size_t)(NB + b) * (TOPK * HALF) + (size_t)t * HALF) * (DIM / 4);

#pragma unroll 5
        for (int i = threadIdx.x; i < PLEN * DIM / 4; i += 256) {
            float4 v = __ldg(src + i);
            if (i < halfN) out4[base0 + i] = v;
            else           out4[base1 + (i - halfN)] = v;
        }
    }
}

// ---------------------------------------------------------------------------
extern "C" void kernel_launch(void* const* d_in, const int* in_sizes, int n_in,
                              void* d_out, int out_size) {
    const float* xq = (const float*)d_in[0];   // x_query [8192,768]
    // d_in[1] = x (unused)
    const float* K  = (const float*)d_in[2];   // [30,768]
    const float* p  = (const float*)d_in[3];   // [30,20,768]
    float*       out = (float*)d_out;          // [2,8192,50,768]

    l2p_onepass_kernel<<<NB, 256>>>(xq, K, p, out);
}